// round 6
// baseline (speedup 1.0000x reference)
#include <cuda_runtime.h>
#include <cuda_fp16.h>

#define NROWS 8192
#define DDIM  512
#define NTRIP 200000
#define BCAP  96      // max triplets per anchor bucket (Poisson mean 24.4; P(>96) ~ 0)

// Scratch (allocation-free rule: __device__ globals)
__device__ __align__(16) __half g_xh [NROWS * DDIM];  // fp16 x rows (8 MB)
__device__ __align__(16) __half g_ynh[NROWS * DDIM];  // fp16 normalized y rows (8 MB)
__device__ float  g_sqx[NROWS];                       // exact fp32 ||x||^2
__device__ double g_accum;
__device__ int    g_cnt[NROWS];                       // bucket counts
__device__ int2   g_slots[NROWS * BCAP];              // (j,k) per bucket slot (6.3 MB)

__device__ __forceinline__ void unpack8(const uint4 v, float* f) {
    float2 a = __half22float2(*(const __half2*)&v.x);
    float2 b = __half22float2(*(const __half2*)&v.y);
    float2 c = __half22float2(*(const __half2*)&v.z);
    float2 d = __half22float2(*(const __half2*)&v.w);
    f[0] = a.x; f[1] = a.y; f[2] = b.x; f[3] = b.y;
    f[4] = c.x; f[5] = c.y; f[6] = d.x; f[7] = d.y;
}

// ---------------------------------------------------------------------------
// prep: warp-per-row. ||x||^2 (fp32 exact), x -> fp16, y normalized -> fp16.
// Also zeroes g_cnt and g_accum.
// ---------------------------------------------------------------------------
__global__ __launch_bounds__(256)
void prep_kernel(const float* __restrict__ x,
                 const float* __restrict__ y,
                 const float* __restrict__ norm_s) {
    const int warp = threadIdx.x >> 5;
    const int lane = threadIdx.x & 31;
    const int row  = blockIdx.x * 8 + warp;
    const int gid  = blockIdx.x * 256 + threadIdx.x;
    if (gid < NROWS) g_cnt[gid] = 0;
    if (gid == 0)    g_accum = 0.0;

    const float4* xr = (const float4*)(x + (size_t)row * DDIM);
    const float4* yr = (const float4*)(y + (size_t)row * DDIM);

    float4 xv[4], yv[4];
    #pragma unroll
    for (int it = 0; it < 4; ++it) {
        xv[it] = xr[it * 32 + lane];
        yv[it] = yr[it * 32 + lane];
    }

    float sx = 0.f, sy = 0.f;
    #pragma unroll
    for (int it = 0; it < 4; ++it) {
        sx = fmaf(xv[it].x, xv[it].x, sx); sx = fmaf(xv[it].y, xv[it].y, sx);
        sx = fmaf(xv[it].z, xv[it].z, sx); sx = fmaf(xv[it].w, xv[it].w, sx);
        sy = fmaf(yv[it].x, yv[it].x, sy); sy = fmaf(yv[it].y, yv[it].y, sy);
        sy = fmaf(yv[it].z, yv[it].z, sy); sy = fmaf(yv[it].w, yv[it].w, sy);
    }
    #pragma unroll
    for (int off = 16; off; off >>= 1) {
        sx += __shfl_xor_sync(0xFFFFFFFFu, sx, off);
        sy += __shfl_xor_sync(0xFFFFFFFFu, sy, off);
    }
    if (lane == 0) g_sqx[row] = sx;

    const float scale = norm_s[0] * rsqrtf(sy);

    uint2* xo = (uint2*)(g_xh  + (size_t)row * DDIM);
    uint2* yo = (uint2*)(g_ynh + (size_t)row * DDIM);
    #pragma unroll
    for (int it = 0; it < 4; ++it) {
        __half2 hx0 = __floats2half2_rn(xv[it].x, xv[it].y);
        __half2 hx1 = __floats2half2_rn(xv[it].z, xv[it].w);
        uint2 wx; wx.x = *(unsigned*)&hx0; wx.y = *(unsigned*)&hx1;
        xo[it * 32 + lane] = wx;

        __half2 hy0 = __floats2half2_rn(yv[it].x * scale, yv[it].y * scale);
        __half2 hy1 = __floats2half2_rn(yv[it].z * scale, yv[it].w * scale);
        uint2 wy; wy.x = *(unsigned*)&hy0; wy.y = *(unsigned*)&hy1;
        yo[it * 32 + lane] = wy;
    }
}

// ---------------------------------------------------------------------------
// scatter: single pass, 2 triplets per thread; (j,k) into anchor bucket slots.
// ---------------------------------------------------------------------------
__global__ __launch_bounds__(256)
void scatter_kernel(const int* __restrict__ trips) {
    const int base = (blockIdx.x * 256 + threadIdx.x) * 2;
    #pragma unroll
    for (int u = 0; u < 2; ++u) {
        const int t = base + u;
        if (t < NTRIP) {
            const int i = trips[3 * t + 0];
            const int j = trips[3 * t + 1];
            const int k = trips[3 * t + 2];
            const int pos = atomicAdd(&g_cnt[i], 1);
            if (pos < BCAP) {
                int2 jk; jk.x = j; jk.y = k;
                g_slots[i * BCAP + pos] = jk;
            }
        }
    }
}

// ---------------------------------------------------------------------------
// bucket kernel: one CTA per anchor. Anchor rows smem->registers (fp32),
// each warp loops over the bucket's triplets loading only 4 partner rows.
// ---------------------------------------------------------------------------
__device__ __forceinline__ float softplus_f(float z) {
    return fmaxf(z, 0.0f) + log1pf(expf(-fabsf(z)));
}

__global__ __launch_bounds__(256, 4)
void bucket_kernel(const float* __restrict__ norm_s) {
    const int b = blockIdx.x;                 // anchor row
    int cnt = g_cnt[b];
    if (cnt == 0) return;                     // uniform across CTA
    if (cnt > BCAP) cnt = BCAP;

    const int tid  = threadIdx.x;
    const int warp = tid >> 5;
    const int lane = tid & 31;

    __shared__ uint4 s_anchor[128];           // 64 x + 64 yn (2 KB)
    __shared__ float s_warp[8];

    if (tid < 64)
        s_anchor[tid] = ((const uint4*)(g_xh + (size_t)b * DDIM))[tid];
    else if (tid < 128)
        s_anchor[tid] = ((const uint4*)(g_ynh + (size_t)b * DDIM))[tid - 64];
    __syncthreads();

    // per-lane anchor slices, unpacked to fp32 once
    float ax[16], ay[16];
    #pragma unroll
    for (int it = 0; it < 2; ++it) {
        unpack8(s_anchor[it * 32 + lane],      ax + 8 * it);
        unpack8(s_anchor[64 + it * 32 + lane], ay + 8 * it);
    }

    const float sqi  = g_sqx[b];
    const float s    = norm_s[0];
    const float s2x2 = 2.0f * s * s;          // ||y_n||^2 == norm_s^2 per row

    float local = 0.0f;
    for (int w = warp; w < cnt; w += 8) {
        const int2 jk = g_slots[b * BCAP + w];
        const int j = jk.x, k = jk.y;

        const uint4* xj = (const uint4*)(g_xh  + (size_t)j * DDIM);
        const uint4* xk = (const uint4*)(g_xh  + (size_t)k * DDIM);
        const uint4* yj = (const uint4*)(g_ynh + (size_t)j * DDIM);
        const uint4* yk = (const uint4*)(g_ynh + (size_t)k * DDIM);

        float axj = 0.f, axk = 0.f, ayj = 0.f, ayk = 0.f;
        #pragma unroll
        for (int it = 0; it < 2; ++it) {
            const int c = it * 32 + lane;     // 64 uint4 per row
            const uint4 vb = __ldg(&xj[c]);
            const uint4 vd = __ldg(&xk[c]);
            const uint4 vq = __ldg(&yj[c]);
            const uint4 vr = __ldg(&yk[c]);
            float bb[8], dd[8], qq[8], rr[8];
            unpack8(vb, bb); unpack8(vd, dd);
            unpack8(vq, qq); unpack8(vr, rr);
            #pragma unroll
            for (int e = 0; e < 8; ++e) {
                const float a = ax[8 * it + e];
                const float p = ay[8 * it + e];
                axj = fmaf(a, bb[e], axj);
                axk = fmaf(a, dd[e], axk);
                ayj = fmaf(p, qq[e], ayj);
                ayk = fmaf(p, rr[e], ayk);
            }
        }
        #pragma unroll
        for (int off = 16; off; off >>= 1) {
            axj += __shfl_xor_sync(0xFFFFFFFFu, axj, off);
            axk += __shfl_xor_sync(0xFFFFFFFFu, axk, off);
            ayj += __shfl_xor_sync(0xFFFFFFFFu, ayj, off);
            ayk += __shfl_xor_sync(0xFFFFFFFFu, ayk, off);
        }
        if (lane == 0) {
            const float sqj = g_sqx[j];
            const float sqk = g_sqx[k];
            const float dij = fmaxf(sqi + sqj - 2.0f * axj, 0.0f);
            const float dik = fmaxf(sqi + sqk - 2.0f * axk, 0.0f);
            const float tij = fmaxf(s2x2 - 2.0f * ayj, 0.0f);
            const float tik = fmaxf(s2x2 - 2.0f * ayk, 0.0f);
            local += softplus_f(dij - dik) + softplus_f(tij - tik);
        }
    }

    if (lane == 0) s_warp[warp] = local;
    __syncthreads();
    if (tid == 0) {
        float sum = 0.f;
        #pragma unroll
        for (int w = 0; w < 8; ++w) sum += s_warp[w];
        atomicAdd(&g_accum, (double)sum);
    }
}

__global__ void finalize_kernel(float* __restrict__ out) {
    out[0] = (float)(g_accum * (1.0 / (double)NTRIP));
}

// ---------------------------------------------------------------------------
extern "C" void kernel_launch(void* const* d_in, const int* in_sizes, int n_in,
                              void* d_out, int out_size) {
    const float* x      = (const float*)d_in[0];
    const float* y      = (const float*)d_in[1];
    const float* norm_s = (const float*)d_in[2];
    const int*   trips  = (const int*)d_in[3];
    float*       out    = (float*)d_out;

    prep_kernel<<<NROWS / 8, 256>>>(x, y, norm_s);
    scatter_kernel<<<(NTRIP / 2 + 255) / 256, 256>>>(trips);
    bucket_kernel<<<NROWS, 256>>>(norm_s);
    finalize_kernel<<<1, 1>>>(out);
}

// round 7
// speedup vs baseline: 1.7613x; 1.7613x over previous
#include <cuda_runtime.h>
#include <cuda_fp16.h>

#define NROWS 8192
#define DDIM  512
#define NTRIP 200000
#define NBLK  ((NTRIP + 7) / 8)

// Scratch (allocation-free rule: __device__ globals)
// int8 tables: element order within a row is permuted (lane-interleaved) but the
// SAME permutation for every row, so dot products are preserved.
__device__ __align__(16) signed char g_x8[NROWS * DDIM];  // 4 MB
__device__ __align__(16) signed char g_y8[NROWS * DDIM];  // 4 MB (normalized y dir)
__device__ float  g_sqx[NROWS];    // exact fp32 ||x||^2
__device__ float  g_scx[NROWS];    // x dequant scale  (max|x| / 127)
__device__ float  g_scy[NROWS];    // y_n dequant scale (max|y_n| / 127)
__device__ double g_accum;
__device__ unsigned g_done;        // last-block counter (starts 0, reset after use)

__device__ __forceinline__ int pack4(const float4 v, const float inv) {
    int q0 = __float2int_rn(v.x * inv);
    int q1 = __float2int_rn(v.y * inv);
    int q2 = __float2int_rn(v.z * inv);
    int q3 = __float2int_rn(v.w * inv);
    q0 = max(-127, min(127, q0)); q1 = max(-127, min(127, q1));
    q2 = max(-127, min(127, q2)); q3 = max(-127, min(127, q3));
    return (q0 & 0xFF) | ((q1 & 0xFF) << 8) | ((q2 & 0xFF) << 16) | (q3 << 24);
}

// ---------------------------------------------------------------------------
// prep: warp-per-row. Exact ||x||^2; per-row max -> int8 quantize x and y_n.
// ---------------------------------------------------------------------------
__global__ __launch_bounds__(256)
void prep_kernel(const float* __restrict__ x,
                 const float* __restrict__ y,
                 const float* __restrict__ norm_s) {
    const int warp = threadIdx.x >> 5;
    const int lane = threadIdx.x & 31;
    const int row  = blockIdx.x * 8 + warp;
    if (blockIdx.x == 0 && threadIdx.x == 0) { g_accum = 0.0; g_done = 0u; }

    const float4* xr = (const float4*)(x + (size_t)row * DDIM);
    const float4* yr = (const float4*)(y + (size_t)row * DDIM);

    float4 xv[4], yv[4];
    #pragma unroll
    for (int it = 0; it < 4; ++it) {
        xv[it] = xr[it * 32 + lane];
        yv[it] = yr[it * 32 + lane];
    }

    float sx = 0.f, sy = 0.f, mx = 0.f, my = 0.f;
    #pragma unroll
    for (int it = 0; it < 4; ++it) {
        sx = fmaf(xv[it].x, xv[it].x, sx); sx = fmaf(xv[it].y, xv[it].y, sx);
        sx = fmaf(xv[it].z, xv[it].z, sx); sx = fmaf(xv[it].w, xv[it].w, sx);
        sy = fmaf(yv[it].x, yv[it].x, sy); sy = fmaf(yv[it].y, yv[it].y, sy);
        sy = fmaf(yv[it].z, yv[it].z, sy); sy = fmaf(yv[it].w, yv[it].w, sy);
        mx = fmaxf(mx, fmaxf(fmaxf(fabsf(xv[it].x), fabsf(xv[it].y)),
                             fmaxf(fabsf(xv[it].z), fabsf(xv[it].w))));
        my = fmaxf(my, fmaxf(fmaxf(fabsf(yv[it].x), fabsf(yv[it].y)),
                             fmaxf(fabsf(yv[it].z), fabsf(yv[it].w))));
    }
    #pragma unroll
    for (int off = 16; off; off >>= 1) {
        sx += __shfl_xor_sync(0xFFFFFFFFu, sx, off);
        sy += __shfl_xor_sync(0xFFFFFFFFu, sy, off);
        mx = fmaxf(mx, __shfl_xor_sync(0xFFFFFFFFu, mx, off));
        my = fmaxf(my, __shfl_xor_sync(0xFFFFFFFFu, my, off));
    }

    const float nrm = norm_s[0] * rsqrtf(sy);   // y_n = y * nrm
    if (lane == 0) {
        g_sqx[row] = sx;
        g_scx[row] = mx * (1.0f / 127.0f);
        g_scy[row] = my * nrm * (1.0f / 127.0f); // max|y_n| / 127
    }

    const float invx = 127.0f / mx;   // rows of gaussians: mx > 0 always
    const float invy = 127.0f / my;   // y_n quantization == direction quantization

    int4 px, py;
    px.x = pack4(xv[0], invx); px.y = pack4(xv[1], invx);
    px.z = pack4(xv[2], invx); px.w = pack4(xv[3], invx);
    py.x = pack4(yv[0], invy); py.y = pack4(yv[1], invy);
    py.z = pack4(yv[2], invy); py.w = pack4(yv[3], invy);
    ((int4*)(g_x8 + (size_t)row * DDIM))[lane] = px;
    ((int4*)(g_y8 + (size_t)row * DDIM))[lane] = py;
}

// ---------------------------------------------------------------------------
// triplet kernel: one warp per triplet. 6 x LDG.128 (one per row), DP4A dots
// (exact int arithmetic), REDUX warp reduce, scale in fp32 at the end.
// Last block writes the output (no separate finalize launch).
// ---------------------------------------------------------------------------
__device__ __forceinline__ float softplus_f(float z) {
    return fmaxf(z, 0.0f) + log1pf(expf(-fabsf(z)));
}

__global__ __launch_bounds__(256, 8)
void triplet_kernel(const int* __restrict__ trips,
                    const float* __restrict__ norm_s,
                    float* __restrict__ out) {
    const int warp = threadIdx.x >> 5;
    const int lane = threadIdx.x & 31;
    const int t = blockIdx.x * 8 + warp;

    float val = 0.0f;
    if (t < NTRIP) {
        const int i = __ldg(&trips[3 * t + 0]);
        const int j = __ldg(&trips[3 * t + 1]);
        const int k = __ldg(&trips[3 * t + 2]);

        const int4 va = ((const int4*)(g_x8 + (size_t)i * DDIM))[lane];
        const int4 vb = ((const int4*)(g_x8 + (size_t)j * DDIM))[lane];
        const int4 vd = ((const int4*)(g_x8 + (size_t)k * DDIM))[lane];
        const int4 vp = ((const int4*)(g_y8 + (size_t)i * DDIM))[lane];
        const int4 vq = ((const int4*)(g_y8 + (size_t)j * DDIM))[lane];
        const int4 vr = ((const int4*)(g_y8 + (size_t)k * DDIM))[lane];

        int axj = 0, axk = 0, ayj = 0, ayk = 0;
        axj = __dp4a(va.x, vb.x, axj); axj = __dp4a(va.y, vb.y, axj);
        axj = __dp4a(va.z, vb.z, axj); axj = __dp4a(va.w, vb.w, axj);
        axk = __dp4a(va.x, vd.x, axk); axk = __dp4a(va.y, vd.y, axk);
        axk = __dp4a(va.z, vd.z, axk); axk = __dp4a(va.w, vd.w, axk);
        ayj = __dp4a(vp.x, vq.x, ayj); ayj = __dp4a(vp.y, vq.y, ayj);
        ayj = __dp4a(vp.z, vq.z, ayj); ayj = __dp4a(vp.w, vq.w, ayj);
        ayk = __dp4a(vp.x, vr.x, ayk); ayk = __dp4a(vp.y, vr.y, ayk);
        ayk = __dp4a(vp.z, vr.z, ayk); ayk = __dp4a(vp.w, vr.w, ayk);

        axj = __reduce_add_sync(0xFFFFFFFFu, axj);
        axk = __reduce_add_sync(0xFFFFFFFFu, axk);
        ayj = __reduce_add_sync(0xFFFFFFFFu, ayj);
        ayk = __reduce_add_sync(0xFFFFFFFFu, ayk);

        if (lane == 0) {
            const float sxi = g_scx[i], sxj = g_scx[j], sxk = g_scx[k];
            const float syi = g_scy[i], syj = g_scy[j], syk = g_scy[k];
            const float dotxj = (float)axj * (sxi * sxj);
            const float dotxk = (float)axk * (sxi * sxk);
            const float dotyj = (float)ayj * (syi * syj);
            const float dotyk = (float)ayk * (syi * syk);

            const float sqi = g_sqx[i];
            const float sqj = g_sqx[j];
            const float sqk = g_sqx[k];
            const float dij = fmaxf(sqi + sqj - 2.0f * dotxj, 0.0f);
            const float dik = fmaxf(sqi + sqk - 2.0f * dotxk, 0.0f);
            const float s   = norm_s[0];
            const float s2x2 = 2.0f * s * s;   // ||y_n||^2 == norm_s^2 per row
            const float tij = fmaxf(s2x2 - 2.0f * dotyj, 0.0f);
            const float tik = fmaxf(s2x2 - 2.0f * dotyk, 0.0f);
            val = softplus_f(dij - dik) + softplus_f(tij - tik);
        }
    }

    __shared__ float sh[8];
    if (lane == 0) sh[warp] = val;
    __syncthreads();
    if (threadIdx.x == 0) {
        float s = 0.f;
        #pragma unroll
        for (int w = 0; w < 8; ++w) s += sh[w];
        atomicAdd(&g_accum, (double)s);
        __threadfence();
        if (atomicAdd(&g_done, 1u) == (unsigned)(NBLK - 1)) {
            g_done = 0u;   // reset for next graph replay
            out[0] = (float)(g_accum * (1.0 / (double)NTRIP));
        }
    }
}

// ---------------------------------------------------------------------------
extern "C" void kernel_launch(void* const* d_in, const int* in_sizes, int n_in,
                              void* d_out, int out_size) {
    const float* x      = (const float*)d_in[0];
    const float* y      = (const float*)d_in[1];
    const float* norm_s = (const float*)d_in[2];
    const int*   trips  = (const int*)d_in[3];
    float*       out    = (float*)d_out;

    prep_kernel<<<NROWS / 8, 256>>>(x, y, norm_s);
    triplet_kernel<<<NBLK, 256>>>(trips, norm_s, out);
}

// round 8
// speedup vs baseline: 1.9585x; 1.1120x over previous
#include <cuda_runtime.h>

#define NROWS 8192
#define DDIM  512
#define NTRIP 200000
#define NBLK  ((NTRIP + 7) / 8)
#define ROWB  1024      // bytes per interleaved row pair (512 x8 + 512 y8)

// Scratch (allocation-free rule: __device__ globals)
// Interleaved int8 rows: [row][0:512) = x8, [row][512:1024) = y8 (normalized dir).
__device__ __align__(16) signed char g_xy8[NROWS * ROWB];   // 8 MB
__device__ __align__(16) float4      g_meta[NROWS];          // (sqx, scx, scy, 0)
__device__ double g_accum;
__device__ unsigned g_done;

__device__ __forceinline__ int pack4(const float4 v, const float inv) {
    int q0 = __float2int_rn(v.x * inv);
    int q1 = __float2int_rn(v.y * inv);
    int q2 = __float2int_rn(v.z * inv);
    int q3 = __float2int_rn(v.w * inv);
    q0 = max(-127, min(127, q0)); q1 = max(-127, min(127, q1));
    q2 = max(-127, min(127, q2)); q3 = max(-127, min(127, q3));
    return (q0 & 0xFF) | ((q1 & 0xFF) << 8) | ((q2 & 0xFF) << 16) | (q3 << 24);
}

// ---------------------------------------------------------------------------
// prep: warp-per-row. Exact ||x||^2; per-row max -> int8 quantize x and y_n.
// ---------------------------------------------------------------------------
__global__ __launch_bounds__(256)
void prep_kernel(const float* __restrict__ x,
                 const float* __restrict__ y,
                 const float* __restrict__ norm_s) {
    const int warp = threadIdx.x >> 5;
    const int lane = threadIdx.x & 31;
    const int row  = blockIdx.x * 8 + warp;
    if (blockIdx.x == 0 && threadIdx.x == 0) { g_accum = 0.0; g_done = 0u; }

    const float4* xr = (const float4*)(x + (size_t)row * DDIM);
    const float4* yr = (const float4*)(y + (size_t)row * DDIM);

    float4 xv[4], yv[4];
    #pragma unroll
    for (int it = 0; it < 4; ++it) {
        xv[it] = xr[it * 32 + lane];
        yv[it] = yr[it * 32 + lane];
    }

    float sx = 0.f, sy = 0.f, mx = 0.f, my = 0.f;
    #pragma unroll
    for (int it = 0; it < 4; ++it) {
        sx = fmaf(xv[it].x, xv[it].x, sx); sx = fmaf(xv[it].y, xv[it].y, sx);
        sx = fmaf(xv[it].z, xv[it].z, sx); sx = fmaf(xv[it].w, xv[it].w, sx);
        sy = fmaf(yv[it].x, yv[it].x, sy); sy = fmaf(yv[it].y, yv[it].y, sy);
        sy = fmaf(yv[it].z, yv[it].z, sy); sy = fmaf(yv[it].w, yv[it].w, sy);
        mx = fmaxf(mx, fmaxf(fmaxf(fabsf(xv[it].x), fabsf(xv[it].y)),
                             fmaxf(fabsf(xv[it].z), fabsf(xv[it].w))));
        my = fmaxf(my, fmaxf(fmaxf(fabsf(yv[it].x), fabsf(yv[it].y)),
                             fmaxf(fabsf(yv[it].z), fabsf(yv[it].w))));
    }
    #pragma unroll
    for (int off = 16; off; off >>= 1) {
        sx += __shfl_xor_sync(0xFFFFFFFFu, sx, off);
        sy += __shfl_xor_sync(0xFFFFFFFFu, sy, off);
        mx = fmaxf(mx, __shfl_xor_sync(0xFFFFFFFFu, mx, off));
        my = fmaxf(my, __shfl_xor_sync(0xFFFFFFFFu, my, off));
    }

    const float nrm = norm_s[0] * rsqrtf(sy);   // y_n = y * nrm
    if (lane == 0) {
        float4 m;
        m.x = sx;
        m.y = mx * (1.0f / 127.0f);
        m.z = my * nrm * (1.0f / 127.0f);
        m.w = 0.f;
        g_meta[row] = m;
    }

    const float invx = 127.0f / mx;
    const float invy = 127.0f / my;

    int4 px, py;
    px.x = pack4(xv[0], invx); px.y = pack4(xv[1], invx);
    px.z = pack4(xv[2], invx); px.w = pack4(xv[3], invx);
    py.x = pack4(yv[0], invy); py.y = pack4(yv[1], invy);
    py.z = pack4(yv[2], invy); py.w = pack4(yv[3], invy);
    int4* rp = (int4*)(g_xy8 + (size_t)row * ROWB);
    rp[lane]      = px;   // x8 half
    rp[32 + lane] = py;   // y8 half
}

// ---------------------------------------------------------------------------
// triplet kernel: one warp per triplet; DP4A dots; softplus batched to warp 0.
// ---------------------------------------------------------------------------
__device__ __forceinline__ float softplus_f(float z) {
    return fmaxf(z, 0.0f) + log1pf(expf(-fabsf(z)));
}

__global__ __launch_bounds__(256, 8)
void triplet_kernel(const int* __restrict__ trips,
                    const float* __restrict__ norm_s,
                    float* __restrict__ out) {
    const int warp = threadIdx.x >> 5;
    const int lane = threadIdx.x & 31;
    const int t = blockIdx.x * 8 + warp;

    __shared__ float s_args[16];

    float argi = -1e30f, argt = -1e30f;   // softplus(-1e30) == 0
    if (t < NTRIP) {
        const int i = __ldg(&trips[3 * t + 0]);
        const int j = __ldg(&trips[3 * t + 1]);
        const int k = __ldg(&trips[3 * t + 2]);

        const int4* pi = (const int4*)(g_xy8 + (size_t)i * ROWB);
        const int4* pj = (const int4*)(g_xy8 + (size_t)j * ROWB);
        const int4* pk = (const int4*)(g_xy8 + (size_t)k * ROWB);

        const int4 va = pi[lane];
        const int4 vb = pj[lane];
        const int4 vd = pk[lane];
        const int4 vp = pi[32 + lane];
        const int4 vq = pj[32 + lane];
        const int4 vr = pk[32 + lane];

        int axj = 0, axk = 0, ayj = 0, ayk = 0;
        axj = __dp4a(va.x, vb.x, axj); axj = __dp4a(va.y, vb.y, axj);
        axj = __dp4a(va.z, vb.z, axj); axj = __dp4a(va.w, vb.w, axj);
        axk = __dp4a(va.x, vd.x, axk); axk = __dp4a(va.y, vd.y, axk);
        axk = __dp4a(va.z, vd.z, axk); axk = __dp4a(va.w, vd.w, axk);
        ayj = __dp4a(vp.x, vq.x, ayj); ayj = __dp4a(vp.y, vq.y, ayj);
        ayj = __dp4a(vp.z, vq.z, ayj); ayj = __dp4a(vp.w, vq.w, ayj);
        ayk = __dp4a(vp.x, vr.x, ayk); ayk = __dp4a(vp.y, vr.y, ayk);
        ayk = __dp4a(vp.z, vr.z, ayk); ayk = __dp4a(vp.w, vr.w, ayk);

        axj = __reduce_add_sync(0xFFFFFFFFu, axj);
        axk = __reduce_add_sync(0xFFFFFFFFu, axk);
        ayj = __reduce_add_sync(0xFFFFFFFFu, ayj);
        ayk = __reduce_add_sync(0xFFFFFFFFu, ayk);

        if (lane == 0) {
            const float4 mi = __ldg(&g_meta[i]);
            const float4 mj = __ldg(&g_meta[j]);
            const float4 mk = __ldg(&g_meta[k]);
            const float dotxj = (float)axj * (mi.y * mj.y);
            const float dotxk = (float)axk * (mi.y * mk.y);
            const float dotyj = (float)ayj * (mi.z * mj.z);
            const float dotyk = (float)ayk * (mi.z * mk.z);

            const float dij = fmaxf(mi.x + mj.x - 2.0f * dotxj, 0.0f);
            const float dik = fmaxf(mi.x + mk.x - 2.0f * dotxk, 0.0f);
            const float s   = norm_s[0];
            const float s2x2 = 2.0f * s * s;   // ||y_n||^2 == norm_s^2 per row
            const float tij = fmaxf(s2x2 - 2.0f * dotyj, 0.0f);
            const float tik = fmaxf(s2x2 - 2.0f * dotyk, 0.0f);
            argi = dij - dik;
            argt = tij - tik;
        }
    }

    if (lane == 0) {
        s_args[2 * warp + 0] = argi;
        s_args[2 * warp + 1] = argt;
    }
    __syncthreads();

    if (warp == 0) {
        float v = (lane < 16) ? softplus_f(s_args[lane]) : 0.0f;
        #pragma unroll
        for (int off = 16; off; off >>= 1)
            v += __shfl_xor_sync(0xFFFFFFFFu, v, off);
        if (lane == 0) {
            atomicAdd(&g_accum, (double)v);
            __threadfence();
            if (atomicAdd(&g_done, 1u) == (unsigned)(NBLK - 1)) {
                g_done = 0u;   // reset for next graph replay
                out[0] = (float)(g_accum * (1.0 / (double)NTRIP));
            }
        }
    }
}

// ---------------------------------------------------------------------------
extern "C" void kernel_launch(void* const* d_in, const int* in_sizes, int n_in,
                              void* d_out, int out_size) {
    const float* x      = (const float*)d_in[0];
    const float* y      = (const float*)d_in[1];
    const float* norm_s = (const float*)d_in[2];
    const int*   trips  = (const int*)d_in[3];
    float*       out    = (float*)d_out;

    prep_kernel<<<NROWS / 8, 256>>>(x, y, norm_s);
    triplet_kernel<<<NBLK, 256>>>(trips, norm_s, out);
}